// round 1
// baseline (speedup 1.0000x reference)
#include <cuda_runtime.h>
#include <cuda_bf16.h>

// Shapes (fixed): B=32, D=64, N=254, L=16, H=128, P=96
#define NB 32
#define ND 64
#define NN 254
#define NL 16
#define NH 128
#define NP 96
#define PAIRS (NB*ND)          // 2048
#define XPP (NN*NL)            // 4064 floats per (b,d) pair
#define OUT_T_ELEMS (NB*NP*ND) // 196608

// ---- shared precomputed tensors (tiny) ----
__device__ __align__(16) float g_constvec[NH];
__device__ __align__(16) float g_M[NN*NL];   // M[n,l] = pos[n,:] . W_enc[l,:]
__device__ __align__(16) float g_D2[NN];     // pos[n,:] . constvec
__device__ __align__(16) float g_G[NL*NL];   // G[l',l] = W_enc[l',:] . W_enc[l,:]
__device__ __align__(16) float g_u[NL];      // W_enc[l,:] . constvec
__device__ __align__(16) float g_wb[NL];     // W_enc[l,:] . b_enc
__device__ float g_s0;                        // b_enc . constvec

// K1: constvec[h] = N*b_enc[h] + sum_n pos[n,h]
__global__ void k_constvec(const float* __restrict__ pos,
                           const float* __restrict__ b_enc) {
    int h = threadIdx.x;            // 128 threads
    float s = 0.f;
    #pragma unroll 8
    for (int n = 0; n < NN; n++) s += pos[n*NH + h];
    g_constvec[h] = (float)NN * b_enc[h] + s;
}

// K2: all other precomputes. 4607 independent length-128 dot products.
__global__ void k_precomp(const float* __restrict__ pos,
                          const float* __restrict__ W_enc,
                          const float* __restrict__ b_enc) {
    int j = blockIdx.x * blockDim.x + threadIdx.x;
    if (j < NN*NL) {                              // M
        int n = j >> 4, l = j & 15;
        const float* pr = pos + n*NH;
        const float* wr = W_enc + l*NH;
        float a = 0.f;
        #pragma unroll 8
        for (int h = 0; h < NH; h++) a += pr[h]*wr[h];
        g_M[j] = a;
    } else if (j < NN*NL + NN) {                  // D2
        int n = j - NN*NL;
        const float* pr = pos + n*NH;
        float a = 0.f;
        #pragma unroll 8
        for (int h = 0; h < NH; h++) a += pr[h]*g_constvec[h];
        g_D2[n] = a;
    } else if (j < NN*NL + NN + NL*NL) {          // G
        int k = j - (NN*NL + NN);
        int l1 = k >> 4, l2 = k & 15;
        const float* w1 = W_enc + l1*NH;
        const float* w2 = W_enc + l2*NH;
        float a = 0.f;
        #pragma unroll 8
        for (int h = 0; h < NH; h++) a += w1[h]*w2[h];
        g_G[k] = a;
    } else if (j < NN*NL + NN + NL*NL + NL) {     // u
        int l = j - (NN*NL + NN + NL*NL);
        const float* wr = W_enc + l*NH;
        float a = 0.f;
        #pragma unroll 8
        for (int h = 0; h < NH; h++) a += wr[h]*g_constvec[h];
        g_u[l] = a;
    } else if (j < NN*NL + NN + NL*NL + 2*NL) {   // wb
        int l = j - (NN*NL + NN + NL*NL + NL);
        const float* wr = W_enc + l*NH;
        float a = 0.f;
        #pragma unroll 8
        for (int h = 0; h < NH; h++) a += wr[h]*b_enc[h];
        g_wb[l] = a;
    } else if (j == NN*NL + NN + NL*NL + 2*NL) {  // s0
        float a = 0.f;
        #pragma unroll 8
        for (int h = 0; h < NH; h++) a += b_enc[h]*g_constvec[h];
        g_s0 = a;
    }
}

// Main fused kernel: one block per (b,d) pair, 256 threads.
#define XS_STRIDE 17   // padded row stride (odd -> conflict-free strided access)
__global__ __launch_bounds__(256)
void k_main(const float* __restrict__ x,
            const float* __restrict__ W1, const float* __restrict__ b1,
            const float* __restrict__ W2, const float* __restrict__ b2,
            float* __restrict__ out_t, float* __restrict__ x_copy) {
    __shared__ float xs[NN * XS_STRIDE];   // 254*17 = 4318 floats
    __shared__ float sc[NN + 2];           // scores
    __shared__ float red[16][17];
    __shared__ float xsumS[NL];
    __shared__ float vS[NL];
    __shared__ float pooledS[NL];
    __shared__ float hdnS[NH];
    __shared__ float warpsum[8];
    __shared__ float sS, invS;

    const int tid = threadIdx.x;
    const int pid = blockIdx.x;
    const float4* __restrict__ xp4 = (const float4*)(x + (size_t)pid * XPP);
    float4* __restrict__ xc4 = (float4*)(x_copy + (size_t)pid * XPP);

    // Phase 1: load x slice (1016 float4) -> smem (padded) + fused passthrough copy
    #pragma unroll
    for (int it = 0; it < 4; it++) {
        int i = tid + it*256;
        if (i < XPP/4) {
            float4 v = xp4[i];
            xc4[i] = v;
            int n = i >> 2, lb = (i & 3) * 4;
            float* dst = xs + n*XS_STRIDE + lb;
            dst[0] = v.x; dst[1] = v.y; dst[2] = v.z; dst[3] = v.w;
        }
    }
    __syncthreads();

    // Phase 2: xsum[l] = sum_n x[n,l]  (thread = (l, g) with 16 groups)
    {
        int l = tid & 15, g = tid >> 4;
        float s = 0.f;
        for (int n = g; n < NN; n += 16) s += xs[n*XS_STRIDE + l];
        red[g][l] = s;
    }
    __syncthreads();
    if (tid < NL) {
        float s = 0.f;
        #pragma unroll
        for (int g = 0; g < 16; g++) s += red[g][tid];
        xsumS[tid] = s;
    }
    __syncthreads();

    // Phase 3: v = G^T xsum + u ; s = xsum.wb + s0
    if (tid < NL) {
        float a = g_u[tid];
        #pragma unroll
        for (int lp = 0; lp < NL; lp++) a += xsumS[lp] * g_G[lp*NL + tid];
        vS[tid] = a;
    }
    if (tid == 16) {
        float a = g_s0;
        #pragma unroll
        for (int l = 0; l < NL; l++) a += xsumS[l] * g_wb[l];
        sS = a;
    }
    __syncthreads();

    // Phase 4: score[n] = s + D2[n] + x[n].v + xsum.M[n]
    float myabs = 0.f;
    if (tid < NN) {
        const float* xr = xs + tid*XS_STRIDE;
        const float4* Mr4 = (const float4*)(g_M + tid*NL);
        float a = sS + g_D2[tid];
        #pragma unroll
        for (int q = 0; q < 4; q++) {
            float4 m = Mr4[q];
            int l = q*4;
            a += xr[l+0]*vS[l+0] + xsumS[l+0]*m.x;
            a += xr[l+1]*vS[l+1] + xsumS[l+1]*m.y;
            a += xr[l+2]*vS[l+2] + xsumS[l+2]*m.z;
            a += xr[l+3]*vS[l+3] + xsumS[l+3]*m.w;
        }
        sc[tid] = a;
        myabs = fabsf(a);
    }
    // deterministic reduction of sum|score|
    #pragma unroll
    for (int off = 16; off; off >>= 1)
        myabs += __shfl_down_sync(0xffffffffu, myabs, off);
    if ((tid & 31) == 0) warpsum[tid >> 5] = myabs;
    __syncthreads();
    if (tid == 0) {
        float t = 0.f;
        #pragma unroll
        for (int w = 0; w < 8; w++) t += warpsum[w];
        invS = 1.0f / t;
    }
    __syncthreads();

    // Phase 5: pooled[l] = invS * sum_n x[n,l]*score[n]
    {
        int l = tid & 15, g = tid >> 4;
        float s = 0.f;
        for (int n = g; n < NN; n += 16) s += xs[n*XS_STRIDE + l] * sc[n];
        red[g][l] = s;
    }
    __syncthreads();
    if (tid < NL) {
        float s = 0.f;
        #pragma unroll
        for (int g = 0; g < 16; g++) s += red[g][tid];
        pooledS[tid] = s * invS;
    }
    __syncthreads();

    // Phase 6: hidden = leaky_relu(pooled @ W1 + b1, 0.2)
    if (tid < NH) {
        float a = b1[tid];
        #pragma unroll
        for (int l = 0; l < NL; l++) a += pooledS[l] * W1[l*NH + tid];
        hdnS[tid] = a > 0.f ? a : 0.2f * a;
    }
    __syncthreads();

    // Phase 7: out[p] = hidden @ W2 + b2 ; write transposed (B,P,D)
    if (tid < NP) {
        float a = b2[tid];
        #pragma unroll 16
        for (int h = 0; h < NH; h++) a += hdnS[h] * W2[h*NP + tid];
        int b = pid >> 6, d = pid & 63;
        out_t[b*(NP*ND) + tid*ND + d] = a;
    }
}

extern "C" void kernel_launch(void* const* d_in, const int* in_sizes, int n_in,
                              void* d_out, int out_size) {
    const float* x     = (const float*)d_in[0];
    const float* W_enc = (const float*)d_in[1];
    const float* b_enc = (const float*)d_in[2];
    const float* W1    = (const float*)d_in[3];
    const float* b1    = (const float*)d_in[4];
    const float* W2    = (const float*)d_in[5];
    const float* b2    = (const float*)d_in[6];
    const float* pos   = (const float*)d_in[7];

    float* out   = (float*)d_out;          // (B,P,D) first
    float* xcopy = out + OUT_T_ELEMS;      // then p = x passthrough

    k_constvec<<<1, NH>>>(pos, b_enc);
    k_precomp<<<20, 256>>>(pos, W_enc, b_enc);
    k_main<<<PAIRS, 256>>>(x, W1, b1, W2, b2, out, xcopy);
}

// round 2
// speedup vs baseline: 1.3045x; 1.3045x over previous
#include <cuda_runtime.h>
#include <cuda_bf16.h>

// Shapes (fixed): B=32, D=64, N=254, L=16, H=128, P=96
#define NB 32
#define ND 64
#define NN 254
#define NL 16
#define NH 128
#define NP 96
#define PAIRS (NB*ND)          // 2048
#define XPP (NN*NL)            // 4064 floats per (b,d) pair
#define OUT_T_ELEMS (NB*NP*ND) // 196608

// ---- shared precomputed tensors (tiny) ----
__device__ __align__(16) float g_constvec[NH];
__device__ __align__(16) float g_M[NN*NL];   // M[n,l] = pos[n,:] . W_enc[l,:]
__device__ __align__(16) float g_D2[NN];     // pos[n,:] . constvec
__device__ __align__(16) float g_G[NL*NL];   // G[l',l] = W_enc[l',:] . W_enc[l,:]
__device__ __align__(16) float g_u[NL];      // W_enc[l,:] . constvec
__device__ __align__(16) float g_wb[NL];     // W_enc[l,:] . b_enc
__device__ float g_s0;                        // b_enc . constvec
__device__ __align__(16) float g_pooled[PAIRS*NL]; // scratch: pooled per pair

// K1: constvec[h] = N*b_enc[h] + sum_n pos[n,h]
// 16 blocks x 256 threads; warp w of block b handles column h = b*8+w.
__global__ __launch_bounds__(256) void k_constvec(const float* __restrict__ pos,
                                                  const float* __restrict__ b_enc) {
    int w = threadIdx.x >> 5, lane = threadIdx.x & 31;
    int h = blockIdx.x * 8 + w;
    float s = 0.f;
    #pragma unroll
    for (int k = 0; k < 8; k++) {
        int n = lane + 32*k;
        if (n < NN) s += pos[n*NH + h];
    }
    #pragma unroll
    for (int off = 16; off; off >>= 1)
        s += __shfl_down_sync(0xffffffffu, s, off);
    if (lane == 0) g_constvec[h] = (float)NN * b_enc[h] + s;
}

// vectorized length-128 dot with 4 accumulators
__device__ __forceinline__ float dot128(const float4* __restrict__ a,
                                        const float4* __restrict__ b) {
    float s0=0.f, s1=0.f, s2=0.f, s3=0.f;
    #pragma unroll
    for (int i = 0; i < 32; i += 4) {
        float4 a0=a[i],   b0=b[i];
        float4 a1=a[i+1], b1=b[i+1];
        float4 a2=a[i+2], b2=b[i+2];
        float4 a3=a[i+3], b3=b[i+3];
        s0 += a0.x*b0.x + a0.y*b0.y + a0.z*b0.z + a0.w*b0.w;
        s1 += a1.x*b1.x + a1.y*b1.y + a1.z*b1.z + a1.w*b1.w;
        s2 += a2.x*b2.x + a2.y*b2.y + a2.z*b2.z + a2.w*b2.w;
        s3 += a3.x*b3.x + a3.y*b3.y + a3.z*b3.z + a3.w*b3.w;
    }
    return (s0+s1)+(s2+s3);
}

// K2: all other precomputes. 4607 independent length-128 dot products.
__global__ void k_precomp(const float* __restrict__ pos,
                          const float* __restrict__ W_enc,
                          const float* __restrict__ b_enc) {
    int j = blockIdx.x * blockDim.x + threadIdx.x;
    const float4* pos4 = (const float4*)pos;
    const float4* W4   = (const float4*)W_enc;
    const float4* cv4  = (const float4*)g_constvec;
    const float4* be4  = (const float4*)b_enc;
    if (j < NN*NL) {                              // M
        int n = j >> 4, l = j & 15;
        g_M[j] = dot128(pos4 + n*32, W4 + l*32);
    } else if (j < NN*NL + NN) {                  // D2
        int n = j - NN*NL;
        g_D2[n] = dot128(pos4 + n*32, cv4);
    } else if (j < NN*NL + NN + NL*NL) {          // G
        int k = j - (NN*NL + NN);
        int l1 = k >> 4, l2 = k & 15;
        g_G[k] = dot128(W4 + l1*32, W4 + l2*32);
    } else if (j < NN*NL + NN + NL*NL + NL) {     // u
        int l = j - (NN*NL + NN + NL*NL);
        g_u[l] = dot128(W4 + l*32, cv4);
    } else if (j < NN*NL + NN + NL*NL + 2*NL) {   // wb
        int l = j - (NN*NL + NN + NL*NL + NL);
        g_wb[l] = dot128(W4 + l*32, be4);
    } else if (j == NN*NL + NN + NL*NL + 2*NL) {  // s0
        g_s0 = dot128(be4, cv4);
    }
}

// Main fused kernel: one block per (b,d) pair, 256 threads.
// Reads x once (streaming), writes x passthrough copy, emits pooled[16].
#define XS_STRIDE 17   // padded row stride
__global__ __launch_bounds__(256)
void k_main(const float* __restrict__ x, float* __restrict__ x_copy) {
    __shared__ float xs[NN * XS_STRIDE];   // 254*17 floats
    __shared__ float sc[NN + 2];           // scores
    __shared__ float red[16][17];
    __shared__ float xsumS[NL];
    __shared__ float vS[NL];
    __shared__ float warpsum[8];
    __shared__ float sS, invS;

    const int tid = threadIdx.x;
    const int pid = blockIdx.x;
    const float4* __restrict__ xp4 = (const float4*)(x + (size_t)pid * XPP);
    float4* __restrict__ xc4 = (float4*)(x_copy + (size_t)pid * XPP);

    // Phase 1: streaming load of x slice -> smem + fused passthrough copy
    #pragma unroll
    for (int it = 0; it < 4; it++) {
        int i = tid + it*256;
        if (i < XPP/4) {
            float4 v = __ldcs(xp4 + i);
            __stcs(xc4 + i, v);
            int n = i >> 2, lb = (i & 3) * 4;
            float* dst = xs + n*XS_STRIDE + lb;
            dst[0] = v.x; dst[1] = v.y; dst[2] = v.z; dst[3] = v.w;
        }
    }
    __syncthreads();

    // Phase 2: xsum[l] = sum_n x[n,l]
    {
        int l = tid & 15, g = tid >> 4;
        float s = 0.f;
        for (int n = g; n < NN; n += 16) s += xs[n*XS_STRIDE + l];
        red[g][l] = s;
    }
    __syncthreads();
    if (tid < NL) {
        float s = 0.f;
        #pragma unroll
        for (int g = 0; g < 16; g++) s += red[g][tid];
        xsumS[tid] = s;
    }
    __syncthreads();

    // Phase 3: v = G^T xsum + u ; s = xsum.wb + s0
    if (tid < NL) {
        float a = g_u[tid];
        #pragma unroll
        for (int lp = 0; lp < NL; lp++) a += xsumS[lp] * g_G[lp*NL + tid];
        vS[tid] = a;
    }
    if (tid == 16) {
        float a = g_s0;
        #pragma unroll
        for (int l = 0; l < NL; l++) a += xsumS[l] * g_wb[l];
        sS = a;
    }
    __syncthreads();

    // Phase 4: score[n] = s + D2[n] + x[n].v + xsum.M[n]
    float myabs = 0.f;
    if (tid < NN) {
        const float* xr = xs + tid*XS_STRIDE;
        const float4* Mr4 = (const float4*)(g_M + tid*NL);
        float a = sS + g_D2[tid];
        #pragma unroll
        for (int q = 0; q < 4; q++) {
            float4 m = Mr4[q];
            int l = q*4;
            a += xr[l+0]*vS[l+0] + xsumS[l+0]*m.x;
            a += xr[l+1]*vS[l+1] + xsumS[l+1]*m.y;
            a += xr[l+2]*vS[l+2] + xsumS[l+2]*m.z;
            a += xr[l+3]*vS[l+3] + xsumS[l+3]*m.w;
        }
        sc[tid] = a;
        myabs = fabsf(a);
    }
    // deterministic reduction of sum|score|
    #pragma unroll
    for (int off = 16; off; off >>= 1)
        myabs += __shfl_down_sync(0xffffffffu, myabs, off);
    if ((tid & 31) == 0) warpsum[tid >> 5] = myabs;
    __syncthreads();
    if (tid == 0) {
        float t = 0.f;
        #pragma unroll
        for (int w = 0; w < 8; w++) t += warpsum[w];
        invS = 1.0f / t;
    }
    __syncthreads();

    // Phase 5: pooled[l] = invS * sum_n x[n,l]*score[n]
    {
        int l = tid & 15, g = tid >> 4;
        float s = 0.f;
        for (int n = g; n < NN; n += 16) s += xs[n*XS_STRIDE + l] * sc[n];
        red[g][l] = s;
    }
    __syncthreads();
    if (tid < NL) {
        float s = 0.f;
        #pragma unroll
        for (int g = 0; g < 16; g++) s += red[g][tid];
        g_pooled[pid*NL + tid] = s * invS;
    }
}

// Feed-forward: 8 pairs per block, 128 threads. W1 row register-resident,
// W2 loads amortized over 8 pairs.
#define FP 8
__global__ __launch_bounds__(128)
void k_ff(const float* __restrict__ W1, const float* __restrict__ b1,
          const float* __restrict__ W2, const float* __restrict__ b2,
          float* __restrict__ out_t) {
    __shared__ float pool[FP][NL];
    __shared__ float hdn[FP][NH];
    const int tid = threadIdx.x;
    const int pair0 = blockIdx.x * FP;

    // load pooled (8*16 = 128 values, one per thread)
    pool[tid >> 4][tid & 15] = g_pooled[pair0*NL + tid];
    __syncthreads();

    // hidden: thread tid = h, all 8 pairs
    {
        float w1r[NL];
        #pragma unroll
        for (int l = 0; l < NL; l++) w1r[l] = W1[l*NH + tid];
        float bb = b1[tid];
        #pragma unroll
        for (int p = 0; p < FP; p++) {
            float a = bb;
            #pragma unroll
            for (int l = 0; l < NL; l++) a += pool[p][l] * w1r[l];
            hdn[p][tid] = a > 0.f ? a : 0.2f * a;
        }
    }
    __syncthreads();

    // out: threads 0..95 = p-index, 8 pairs each
    if (tid < NP) {
        float acc[FP];
        float bb = b2[tid];
        #pragma unroll
        for (int p = 0; p < FP; p++) acc[p] = bb;
        #pragma unroll 8
        for (int h = 0; h < NH; h++) {
            float w = W2[h*NP + tid];
            #pragma unroll
            for (int p = 0; p < FP; p++) acc[p] += hdn[p][h] * w;
        }
        #pragma unroll
        for (int p = 0; p < FP; p++) {
            int pid = pair0 + p;
            int b = pid >> 6, d = pid & 63;
            out_t[b*(NP*ND) + tid*ND + d] = acc[p];
        }
    }
}

extern "C" void kernel_launch(void* const* d_in, const int* in_sizes, int n_in,
                              void* d_out, int out_size) {
    const float* x     = (const float*)d_in[0];
    const float* W_enc = (const float*)d_in[1];
    const float* b_enc = (const float*)d_in[2];
    const float* W1    = (const float*)d_in[3];
    const float* b1    = (const float*)d_in[4];
    const float* W2    = (const float*)d_in[5];
    const float* b2    = (const float*)d_in[6];
    const float* pos   = (const float*)d_in[7];

    float* out   = (float*)d_out;          // (B,P,D) first
    float* xcopy = out + OUT_T_ELEMS;      // then p = x passthrough

    k_constvec<<<16, 256>>>(pos, b_enc);
    k_precomp<<<20, 256>>>(pos, W_enc, b_enc);
    k_main<<<PAIRS, 256>>>(x, xcopy);
    k_ff<<<PAIRS/FP, 128>>>(W1, b1, W2, b2, out);
}

// round 3
// speedup vs baseline: 1.4402x; 1.1040x over previous
#include <cuda_runtime.h>
#include <cuda_bf16.h>

// Shapes (fixed): B=32, D=64, N=254, L=16, H=128, P=96
#define NB 32
#define ND 64
#define NN 254
#define NL 16
#define NH 128
#define NP 96
#define PAIRS (NB*ND)          // 2048
#define XPP (NN*NL)            // 4064 floats per (b,d) pair
#define OUT_T_ELEMS (NB*NP*ND) // 196608

// ---- shared precomputed tensors (tiny) ----
__device__ __align__(16) float g_constvec[NH];
__device__ __align__(16) float g_M[NN*NL];   // M[n,l] = pos[n,:] . W_enc[l,:]
__device__ __align__(16) float g_D2[NN];     // pos[n,:] . constvec
__device__ __align__(16) float g_G[NL*NL];   // G[l',l] = W_enc[l',:] . W_enc[l,:]
__device__ __align__(16) float g_u[NL];      // W_enc[l,:] . constvec
__device__ __align__(16) float g_wb[NL];     // W_enc[l,:] . b_enc
__device__ float g_s0;                        // b_enc . constvec

// K1: constvec[h] = N*b_enc[h] + sum_n pos[n,h]
// 16 blocks x 256 threads; warp w of block b handles column h = b*8+w.
__global__ __launch_bounds__(256) void k_constvec(const float* __restrict__ pos,
                                                  const float* __restrict__ b_enc) {
    int w = threadIdx.x >> 5, lane = threadIdx.x & 31;
    int h = blockIdx.x * 8 + w;
    float s = 0.f;
    #pragma unroll
    for (int k = 0; k < 8; k++) {
        int n = lane + 32*k;
        if (n < NN) s += pos[n*NH + h];
    }
    #pragma unroll
    for (int off = 16; off; off >>= 1)
        s += __shfl_down_sync(0xffffffffu, s, off);
    if (lane == 0) g_constvec[h] = (float)NN * b_enc[h] + s;
}

// vectorized length-128 dot with 4 accumulators
__device__ __forceinline__ float dot128(const float4* __restrict__ a,
                                        const float4* __restrict__ b) {
    float s0=0.f, s1=0.f, s2=0.f, s3=0.f;
    #pragma unroll
    for (int i = 0; i < 32; i += 4) {
        float4 a0=a[i],   b0=b[i];
        float4 a1=a[i+1], b1=b[i+1];
        float4 a2=a[i+2], b2=b[i+2];
        float4 a3=a[i+3], b3=b[i+3];
        s0 += a0.x*b0.x + a0.y*b0.y + a0.z*b0.z + a0.w*b0.w;
        s1 += a1.x*b1.x + a1.y*b1.y + a1.z*b1.z + a1.w*b1.w;
        s2 += a2.x*b2.x + a2.y*b2.y + a2.z*b2.z + a2.w*b2.w;
        s3 += a3.x*b3.x + a3.y*b3.y + a3.z*b3.z + a3.w*b3.w;
    }
    return (s0+s1)+(s2+s3);
}

// K2: all other precomputes. 4607 independent length-128 dot products.
__global__ void k_precomp(const float* __restrict__ pos,
                          const float* __restrict__ W_enc,
                          const float* __restrict__ b_enc) {
    int j = blockIdx.x * blockDim.x + threadIdx.x;
    const float4* pos4 = (const float4*)pos;
    const float4* W4   = (const float4*)W_enc;
    const float4* cv4  = (const float4*)g_constvec;
    const float4* be4  = (const float4*)b_enc;
    if (j < NN*NL) {                              // M
        int n = j >> 4, l = j & 15;
        g_M[j] = dot128(pos4 + n*32, W4 + l*32);
    } else if (j < NN*NL + NN) {                  // D2
        int n = j - NN*NL;
        g_D2[n] = dot128(pos4 + n*32, cv4);
    } else if (j < NN*NL + NN + NL*NL) {          // G
        int k = j - (NN*NL + NN);
        int l1 = k >> 4, l2 = k & 15;
        g_G[k] = dot128(W4 + l1*32, W4 + l2*32);
    } else if (j < NN*NL + NN + NL*NL + NL) {     // u
        int l = j - (NN*NL + NN + NL*NL);
        g_u[l] = dot128(W4 + l*32, cv4);
    } else if (j < NN*NL + NN + NL*NL + 2*NL) {   // wb
        int l = j - (NN*NL + NN + NL*NL + NL);
        g_wb[l] = dot128(W4 + l*32, be4);
    } else if (j == NN*NL + NN + NL*NL + 2*NL) {  // s0
        g_s0 = dot128(be4, cv4);
    }
}

// Fully fused main kernel: one block per (b,d) pair, 128 threads.
// Streams x once (fused passthrough copy), attention-pool, feed-forward,
// writes transposed output. No intermediate global scratch.
#define XS_STRIDE 17   // padded row stride
__global__ __launch_bounds__(128)
void k_main(const float* __restrict__ x, float* __restrict__ x_copy,
            const float* __restrict__ W1, const float* __restrict__ b1,
            const float* __restrict__ W2, const float* __restrict__ b2,
            float* __restrict__ out_t) {
    __shared__ float xs[NN * XS_STRIDE];   // 254*17 floats = 17.3KB
    __shared__ float sc[NN + 2];           // scores
    __shared__ float red[8][17];
    __shared__ float xsumS[NL];
    __shared__ float vS[NL];
    __shared__ float pooledS[NL];
    __shared__ float hdnS[NH];
    __shared__ float warpsum[4];
    __shared__ float sS, invS;

    const int tid = threadIdx.x;
    const int pid = blockIdx.x;
    const float4* __restrict__ xp4 = (const float4*)(x + (size_t)pid * XPP);
    float4* __restrict__ xc4 = (float4*)(x_copy + (size_t)pid * XPP);

    // Phase 1: streaming load of x slice -> smem + fused passthrough copy.
    // 1016 float4 over 128 threads: 8 per thread, all independent (MLP=8).
    #pragma unroll
    for (int it = 0; it < 8; it++) {
        int i = tid + it*128;
        if (i < XPP/4) {
            float4 v = __ldcs(xp4 + i);
            __stcs(xc4 + i, v);
            int n = i >> 2, lb = (i & 3) * 4;
            float* dst = xs + n*XS_STRIDE + lb;
            dst[0] = v.x; dst[1] = v.y; dst[2] = v.z; dst[3] = v.w;
        }
    }
    __syncthreads();

    // Phase 2: xsum[l] = sum_n x[n,l]   (thread = (l, g) with 8 groups)
    {
        int l = tid & 15, g = tid >> 4;
        float s0 = 0.f, s1 = 0.f, s2 = 0.f, s3 = 0.f;
        int n = g;
        for (; n + 24 < NN; n += 32) {
            s0 += xs[(n     )*XS_STRIDE + l];
            s1 += xs[(n +  8)*XS_STRIDE + l];
            s2 += xs[(n + 16)*XS_STRIDE + l];
            s3 += xs[(n + 24)*XS_STRIDE + l];
        }
        for (; n < NN; n += 8) s0 += xs[n*XS_STRIDE + l];
        red[g][l] = (s0+s1)+(s2+s3);
    }
    __syncthreads();
    if (tid < NL) {
        float s = 0.f;
        #pragma unroll
        for (int g = 0; g < 8; g++) s += red[g][tid];
        xsumS[tid] = s;
    }
    __syncthreads();

    // Phase 3: v = G^T xsum + u ; s = xsum.wb + s0
    if (tid < NL) {
        float a = g_u[tid];
        #pragma unroll
        for (int lp = 0; lp < NL; lp++) a += xsumS[lp] * g_G[lp*NL + tid];
        vS[tid] = a;
    }
    if (tid == 16) {
        float a = g_s0;
        #pragma unroll
        for (int l = 0; l < NL; l++) a += xsumS[l] * g_wb[l];
        sS = a;
    }
    __syncthreads();

    // Phase 4: score[n] = s + D2[n] + x[n].v + xsum.M[n]   (2 rows per thread)
    float myabs = 0.f;
    #pragma unroll
    for (int r = 0; r < 2; r++) {
        int n = tid + r*128;
        if (n < NN) {
            const float* xr = xs + n*XS_STRIDE;
            const float4* Mr4 = (const float4*)(g_M + n*NL);
            float a = sS + g_D2[n];
            #pragma unroll
            for (int q = 0; q < 4; q++) {
                float4 m = Mr4[q];
                int l = q*4;
                a += xr[l+0]*vS[l+0] + xsumS[l+0]*m.x;
                a += xr[l+1]*vS[l+1] + xsumS[l+1]*m.y;
                a += xr[l+2]*vS[l+2] + xsumS[l+2]*m.z;
                a += xr[l+3]*vS[l+3] + xsumS[l+3]*m.w;
            }
            sc[n] = a;
            myabs += fabsf(a);
        }
    }
    // deterministic reduction of sum|score|
    #pragma unroll
    for (int off = 16; off; off >>= 1)
        myabs += __shfl_down_sync(0xffffffffu, myabs, off);
    if ((tid & 31) == 0) warpsum[tid >> 5] = myabs;
    __syncthreads();
    if (tid == 0) {
        float t = (warpsum[0] + warpsum[1]) + (warpsum[2] + warpsum[3]);
        invS = 1.0f / t;
    }
    __syncthreads();

    // Phase 5: pooled[l] = invS * sum_n x[n,l]*score[n]
    {
        int l = tid & 15, g = tid >> 4;
        float s0 = 0.f, s1 = 0.f, s2 = 0.f, s3 = 0.f;
        int n = g;
        for (; n + 24 < NN; n += 32) {
            s0 += xs[(n     )*XS_STRIDE + l] * sc[n];
            s1 += xs[(n +  8)*XS_STRIDE + l] * sc[n + 8];
            s2 += xs[(n + 16)*XS_STRIDE + l] * sc[n + 16];
            s3 += xs[(n + 24)*XS_STRIDE + l] * sc[n + 24];
        }
        for (; n < NN; n += 8) s0 += xs[n*XS_STRIDE + l] * sc[n];
        red[g][l] = (s0+s1)+(s2+s3);
    }
    __syncthreads();
    if (tid < NL) {
        float s = 0.f;
        #pragma unroll
        for (int g = 0; g < 8; g++) s += red[g][tid];
        pooledS[tid] = s * invS;
    }
    __syncthreads();

    // Phase 6: hidden = leaky_relu(pooled @ W1 + b1, 0.2)   (tid = h)
    {
        float a = b1[tid];
        #pragma unroll
        for (int l = 0; l < NL; l++) a += pooledS[l] * __ldg(W1 + l*NH + tid);
        hdnS[tid] = a > 0.f ? a : 0.2f * a;
    }
    __syncthreads();

    // Phase 7: out[p] = hidden @ W2 + b2 ; write transposed (B,P,D)
    if (tid < NP) {
        float a0 = b2[tid], a1 = 0.f, a2 = 0.f, a3 = 0.f;
        #pragma unroll 4
        for (int h = 0; h < NH; h += 4) {
            a0 += hdnS[h+0] * __ldg(W2 + (h+0)*NP + tid);
            a1 += hdnS[h+1] * __ldg(W2 + (h+1)*NP + tid);
            a2 += hdnS[h+2] * __ldg(W2 + (h+2)*NP + tid);
            a3 += hdnS[h+3] * __ldg(W2 + (h+3)*NP + tid);
        }
        int b = pid >> 6, d = pid & 63;
        out_t[b*(NP*ND) + tid*ND + d] = (a0+a1)+(a2+a3);
    }
}

extern "C" void kernel_launch(void* const* d_in, const int* in_sizes, int n_in,
                              void* d_out, int out_size) {
    const float* x     = (const float*)d_in[0];
    const float* W_enc = (const float*)d_in[1];
    const float* b_enc = (const float*)d_in[2];
    const float* W1    = (const float*)d_in[3];
    const float* b1    = (const float*)d_in[4];
    const float* W2    = (const float*)d_in[5];
    const float* b2    = (const float*)d_in[6];
    const float* pos   = (const float*)d_in[7];

    float* out   = (float*)d_out;          // (B,P,D) first
    float* xcopy = out + OUT_T_ELEMS;      // then p = x passthrough

    k_constvec<<<16, 256>>>(pos, b_enc);
    k_precomp<<<20, 256>>>(pos, W_enc, b_enc);
    k_main<<<PAIRS, 128>>>(x, xcopy, W1, b1, W2, b2, out);
}

// round 4
// speedup vs baseline: 2.0044x; 1.3917x over previous
#include <cuda_runtime.h>
#include <cuda_bf16.h>

// Shapes (fixed): B=32, D=64, N=254, L=16, H=128, P=96
#define NB 32
#define ND 64
#define NN 254
#define NL 16
#define NH 128
#define NP 96
#define PAIRS (NB*ND)          // 2048
#define XPP (NN*NL)            // 4064 floats per (b,d) pair
#define OUT_T_ELEMS (NB*NP*ND) // 196608
#define NPRE 38                // producer blocks

// ---- shared precomputed tensors (tiny) ----
__device__ __align__(16) float g_constvec[NH];
__device__ __align__(16) float g_M[NN*NL];   // M[n,l] = pos[n,:] . W_enc[l,:]
__device__ __align__(16) float g_D2[NN];     // pos[n,:] . constvec
__device__ __align__(16) float g_G[NL*NL];   // G[l',l] = W_enc[l',:] . W_enc[l,:]
__device__ __align__(16) float g_u[NL];      // W_enc[l,:] . constvec
__device__ __align__(16) float g_wb[NL];     // W_enc[l,:] . b_enc
__device__ float g_s0;                        // b_enc . constvec
__device__ int g_flag1;                       // constvec ready (monotone across replays)
__device__ int g_done;                        // precompute producers done (monotone)

__device__ __forceinline__ int ld_acq(const int* p) {
    int v;
    asm volatile("ld.acquire.gpu.global.b32 %0, [%1];" : "=r"(v) : "l"(p));
    return v;
}

// vectorized length-128 dot with 4 accumulators
__device__ __forceinline__ float dot128(const float4* __restrict__ a,
                                        const float4* __restrict__ b) {
    float s0=0.f, s1=0.f, s2=0.f, s3=0.f;
    #pragma unroll
    for (int i = 0; i < 32; i += 4) {
        float4 a0=a[i],   b0=b[i];
        float4 a1=a[i+1], b1=b[i+1];
        float4 a2=a[i+2], b2=b[i+2];
        float4 a3=a[i+3], b3=b[i+3];
        s0 += a0.x*b0.x + a0.y*b0.y + a0.z*b0.z + a0.w*b0.w;
        s1 += a1.x*b1.x + a1.y*b1.y + a1.z*b1.z + a1.w*b1.w;
        s2 += a2.x*b2.x + a2.y*b2.y + a2.z*b2.z + a2.w*b2.w;
        s3 += a3.x*b3.x + a3.y*b3.y + a3.z*b3.z + a3.w*b3.w;
    }
    return (s0+s1)+(s2+s3);
}

#define XS_STRIDE 17   // padded row stride
__global__ __launch_bounds__(128)
void k_all(const float* __restrict__ x, float* __restrict__ x_copy,
           const float* __restrict__ W_enc, const float* __restrict__ b_enc,
           const float* __restrict__ pos,
           const float* __restrict__ W1, const float* __restrict__ b1,
           const float* __restrict__ W2, const float* __restrict__ b2,
           float* __restrict__ out_t) {
    __shared__ float xs[NN * XS_STRIDE];   // 254*17 floats
    __shared__ float sc[NN + 2];           // scores
    __shared__ float red4[32][XS_STRIDE];  // reductions (reused)
    __shared__ float xsumS[NL];
    __shared__ float vS[NL];
    __shared__ float pooledS[NL];
    __shared__ float hdnS[NH];
    __shared__ float warpsum[4];
    __shared__ float sS, invS;

    const int tid = threadIdx.x;
    const int pid = blockIdx.x;
    const float4* __restrict__ pos4 = (const float4*)pos;
    const float4* __restrict__ W4   = (const float4*)W_enc;

    // ---------- inline precompute (first NPRE blocks, wave-1 co-resident) ----------
    if (pid < NPRE) {
        if (pid == 0) {
            // constvec[h] = N*b_enc[h] + sum_n pos[n,h]  (coalesced, 4 chains)
            float a0=0.f, a1=0.f, a2=0.f, a3=0.f;
            #pragma unroll 2
            for (int n = 0; n < 252; n += 4) {
                a0 += __ldg(pos + (n+0)*NH + tid);
                a1 += __ldg(pos + (n+1)*NH + tid);
                a2 += __ldg(pos + (n+2)*NH + tid);
                a3 += __ldg(pos + (n+3)*NH + tid);
            }
            a0 += __ldg(pos + 252*NH + tid);
            a1 += __ldg(pos + 253*NH + tid);
            g_constvec[tid] = (float)NN * b_enc[tid] + ((a0+a1)+(a2+a3));
            __threadfence();
            __syncthreads();
            if (tid == 0) atomicAdd(&g_flag1, 1);
        } else if (pid <= 34) {
            int j = (pid-1)*128 + tid;
            if (j < NN*NL) {                         // M
                g_M[j] = dot128(pos4 + (j>>4)*32, W4 + (j&15)*32);
            } else if (j < NN*NL + NL*NL) {          // G
                int k = j - NN*NL;
                g_G[k] = dot128(W4 + (k>>4)*32, W4 + (k&15)*32);
            }
        } else {
            // needs constvec
            if (tid == 0) { while (ld_acq(&g_flag1) == 0) {} }
            __syncthreads();
            const float4* cv4 = (const float4*)g_constvec;
            int j = (pid-35)*128 + tid;
            if (j < NN) {                            // D2
                g_D2[j] = dot128(pos4 + j*32, cv4);
            } else if (j < NN + NL) {                // u
                g_u[j-NN] = dot128(W4 + (j-NN)*32, cv4);
            } else if (j < NN + 2*NL) {              // wb
                g_wb[j-NN-NL] = dot128(W4 + (j-NN-NL)*32, (const float4*)b_enc);
            } else if (j == NN + 2*NL) {             // s0
                g_s0 = dot128((const float4*)b_enc, cv4);
            }
        }
        __threadfence();
        __syncthreads();
        if (tid == 0) atomicAdd(&g_done, 1);
    }

    // ---------- main per-pair work (all 2048 blocks) ----------
    const float4* __restrict__ xp4 = (const float4*)(x + (size_t)pid * XPP);
    float4* __restrict__ xc4 = (float4*)(x_copy + (size_t)pid * XPP);

    // Phase 1: streaming load -> smem + fused passthrough copy + xsum partials.
    // Each thread owns a fixed l-quarter (lb = (tid&3)*4) across its 8 rows.
    float ls0=0.f, ls1=0.f, ls2=0.f, ls3=0.f;
    #pragma unroll
    for (int it = 0; it < 8; it++) {
        int i = tid + it*128;
        if (i < XPP/4) {
            float4 v = __ldcs(xp4 + i);
            __stcs(xc4 + i, v);
            int n = i >> 2, lb = (i & 3) * 4;
            float* dst = xs + n*XS_STRIDE + lb;
            dst[0] = v.x; dst[1] = v.y; dst[2] = v.z; dst[3] = v.w;
            ls0 += v.x; ls1 += v.y; ls2 += v.z; ls3 += v.w;
        }
    }
    {
        int g = tid >> 2, q = (tid & 3) * 4;
        float* r = &red4[g][q];
        r[0] = ls0; r[1] = ls1; r[2] = ls2; r[3] = ls3;
    }
    __syncthreads();

    // Phase 2: finish xsum reduction; overlap with precompute-done spin
    if (tid < NL) {
        float s = 0.f;
        #pragma unroll
        for (int g = 0; g < 32; g++) s += red4[g][tid];
        xsumS[tid] = s;
    }
    if (tid == 64) { while (ld_acq(&g_done) < NPRE) {} }
    __syncthreads();

    // Phase 3: v = G^T xsum + u ; s = xsum.wb + s0
    if (tid < NL) {
        float a = g_u[tid];
        #pragma unroll
        for (int lp = 0; lp < NL; lp++) a += xsumS[lp] * g_G[lp*NL + tid];
        vS[tid] = a;
    }
    if (tid == 16) {
        float a = g_s0;
        #pragma unroll
        for (int l = 0; l < NL; l++) a += xsumS[l] * g_wb[l];
        sS = a;
    }
    __syncthreads();

    // Phase 4: score[n] = s + D2[n] + x[n].v + xsum.M[n]   (2 rows per thread)
    float myabs = 0.f;
    #pragma unroll
    for (int r = 0; r < 2; r++) {
        int n = tid + r*128;
        if (n < NN) {
            const float* xr = xs + n*XS_STRIDE;
            const float4* Mr4 = (const float4*)(g_M + n*NL);
            float a = sS + g_D2[n];
            #pragma unroll
            for (int q = 0; q < 4; q++) {
                float4 m = Mr4[q];
                int l = q*4;
                a += xr[l+0]*vS[l+0] + xsumS[l+0]*m.x;
                a += xr[l+1]*vS[l+1] + xsumS[l+1]*m.y;
                a += xr[l+2]*vS[l+2] + xsumS[l+2]*m.z;
                a += xr[l+3]*vS[l+3] + xsumS[l+3]*m.w;
            }
            sc[n] = a;
            myabs += fabsf(a);
        }
    }
    // deterministic reduction of sum|score|
    #pragma unroll
    for (int off = 16; off; off >>= 1)
        myabs += __shfl_down_sync(0xffffffffu, myabs, off);
    if ((tid & 31) == 0) warpsum[tid >> 5] = myabs;
    __syncthreads();
    if (tid == 0) {
        float t = (warpsum[0] + warpsum[1]) + (warpsum[2] + warpsum[3]);
        invS = 1.0f / t;
    }
    __syncthreads();

    // Phase 5: pooled[l] = invS * sum_n x[n,l]*score[n]
    {
        int l = tid & 15, g = tid >> 4;
        float s0 = 0.f, s1 = 0.f, s2 = 0.f, s3 = 0.f;
        int n = g;
        for (; n + 24 < NN; n += 32) {
            s0 += xs[(n     )*XS_STRIDE + l] * sc[n];
            s1 += xs[(n +  8)*XS_STRIDE + l] * sc[n + 8];
            s2 += xs[(n + 16)*XS_STRIDE + l] * sc[n + 16];
            s3 += xs[(n + 24)*XS_STRIDE + l] * sc[n + 24];
        }
        for (; n < NN; n += 8) s0 += xs[n*XS_STRIDE + l] * sc[n];
        red4[g][l] = (s0+s1)+(s2+s3);
    }
    __syncthreads();
    if (tid < NL) {
        float s = 0.f;
        #pragma unroll
        for (int g = 0; g < 8; g++) s += red4[g][tid];
        pooledS[tid] = s * invS;
    }
    __syncthreads();

    // Phase 6: hidden = leaky_relu(pooled @ W1 + b1, 0.2)   (tid = h)
    {
        float a = b1[tid];
        #pragma unroll
        for (int l = 0; l < NL; l++) a += pooledS[l] * __ldg(W1 + l*NH + tid);
        hdnS[tid] = a > 0.f ? a : 0.2f * a;
    }
    __syncthreads();

    // Phase 7: out[p] = hidden @ W2 + b2 ; write transposed (B,P,D)
    if (tid < NP) {
        float a0 = b2[tid], a1 = 0.f, a2 = 0.f, a3 = 0.f;
        #pragma unroll 4
        for (int h = 0; h < NH; h += 4) {
            a0 += hdnS[h+0] * __ldg(W2 + (h+0)*NP + tid);
            a1 += hdnS[h+1] * __ldg(W2 + (h+1)*NP + tid);
            a2 += hdnS[h+2] * __ldg(W2 + (h+2)*NP + tid);
            a3 += hdnS[h+3] * __ldg(W2 + (h+3)*NP + tid);
        }
        int b = pid >> 6, d = pid & 63;
        out_t[b*(NP*ND) + tid*ND + d] = (a0+a1)+(a2+a3);
    }
}

extern "C" void kernel_launch(void* const* d_in, const int* in_sizes, int n_in,
                              void* d_out, int out_size) {
    const float* x     = (const float*)d_in[0];
    const float* W_enc = (const float*)d_in[1];
    const float* b_enc = (const float*)d_in[2];
    const float* W1    = (const float*)d_in[3];
    const float* b1    = (const float*)d_in[4];
    const float* W2    = (const float*)d_in[5];
    const float* b2    = (const float*)d_in[6];
    const float* pos   = (const float*)d_in[7];

    float* out   = (float*)d_out;          // (B,P,D) first
    float* xcopy = out + OUT_T_ELEMS;      // then p = x passthrough

    k_all<<<PAIRS, 128>>>(x, xcopy, W_enc, b_enc, pos, W1, b1, W2, b2, out);
}

// round 5
// speedup vs baseline: 2.0421x; 1.0188x over previous
#include <cuda_runtime.h>
#include <cuda_bf16.h>

// Shapes (fixed): B=32, D=64, N=254, L=16, H=128, P=96
#define NB 32
#define ND 64
#define NN 254
#define NL 16
#define NH 128
#define NP 96
#define PAIRS (NB*ND)          // 2048
#define XPP (NN*NL)            // 4064 floats per (b,d) pair
#define OUT_T_ELEMS (NB*NP*ND) // 196608
#define NPRE 38                // producer blocks

// ---- shared precomputed tensors (tiny) ----
__device__ __align__(16) float g_constvec[NH];
__device__ __align__(16) float g_M[NN*NL];   // M[n,l] = pos[n,:] . W_enc[l,:]
__device__ __align__(16) float g_D2[NN];     // pos[n,:] . constvec
__device__ __align__(16) float g_G[NL*NL];   // G[l',l] = W_enc[l',:] . W_enc[l,:]
__device__ __align__(16) float g_u[NL];      // W_enc[l,:] . constvec
__device__ __align__(16) float g_wb[NL];     // W_enc[l,:] . b_enc
__device__ float g_s0;                        // b_enc . constvec
__device__ int g_flag1;                       // constvec ready (monotone across replays)
__device__ int g_done;                        // precompute producers done (monotone)

__device__ __forceinline__ int ld_acq(const int* p) {
    int v;
    asm volatile("ld.acquire.gpu.global.b32 %0, [%1];" : "=r"(v) : "l"(p));
    return v;
}

// vectorized length-128 dot with 4 accumulators
__device__ __forceinline__ float dot128(const float4* __restrict__ a,
                                        const float4* __restrict__ b) {
    float s0=0.f, s1=0.f, s2=0.f, s3=0.f;
    #pragma unroll
    for (int i = 0; i < 32; i += 4) {
        float4 a0=a[i],   b0=b[i];
        float4 a1=a[i+1], b1=b[i+1];
        float4 a2=a[i+2], b2=b[i+2];
        float4 a3=a[i+3], b3=b[i+3];
        s0 += a0.x*b0.x + a0.y*b0.y + a0.z*b0.z + a0.w*b0.w;
        s1 += a1.x*b1.x + a1.y*b1.y + a1.z*b1.z + a1.w*b1.w;
        s2 += a2.x*b2.x + a2.y*b2.y + a2.z*b2.z + a2.w*b2.w;
        s3 += a3.x*b3.x + a3.y*b3.y + a3.z*b3.z + a3.w*b3.w;
    }
    return (s0+s1)+(s2+s3);
}

__global__ __launch_bounds__(128)
void k_all(const float* __restrict__ x, float* __restrict__ x_copy,
           const float* __restrict__ W_enc, const float* __restrict__ b_enc,
           const float* __restrict__ pos,
           const float* __restrict__ W1, const float* __restrict__ b1,
           const float* __restrict__ W2, const float* __restrict__ b2,
           float* __restrict__ out_t) {
    __shared__ float sc[256];                     // scores (254 used, 2 zero pad)
    __shared__ __align__(16) float redq[4][NL];   // per-warp quarter reductions
    __shared__ __align__(16) float xsumS[NL];
    __shared__ __align__(16) float vS[NL];
    __shared__ __align__(16) float pooledS[NL];
    __shared__ float hdnS[NH];
    __shared__ float warpsum[4];
    __shared__ __align__(16) float red7[4][NP];   // phase-7 cross-warp partials
    __shared__ float sS, invS;

    const int tid  = threadIdx.x;
    const int pid  = blockIdx.x;
    const int lane = tid & 31;
    const int wrp  = tid >> 5;
    const int q    = tid & 3;          // l-quarter index
    const int r    = tid >> 2;         // row-within-32 index
    const float4* __restrict__ pos4 = (const float4*)pos;
    const float4* __restrict__ W4   = (const float4*)W_enc;

    // ---------- inline precompute (first NPRE blocks, wave-1 co-resident) ----------
    if (pid < NPRE) {
        if (pid == 0) {
            float a0=0.f, a1=0.f, a2=0.f, a3=0.f;
            #pragma unroll 2
            for (int n = 0; n < 252; n += 4) {
                a0 += __ldg(pos + (n+0)*NH + tid);
                a1 += __ldg(pos + (n+1)*NH + tid);
                a2 += __ldg(pos + (n+2)*NH + tid);
                a3 += __ldg(pos + (n+3)*NH + tid);
            }
            a0 += __ldg(pos + 252*NH + tid);
            a1 += __ldg(pos + 253*NH + tid);
            g_constvec[tid] = (float)NN * b_enc[tid] + ((a0+a1)+(a2+a3));
            __threadfence();
            __syncthreads();
            if (tid == 0) atomicAdd(&g_flag1, 1);
        } else if (pid <= 34) {
            int j = (pid-1)*128 + tid;
            if (j < NN*NL) {                         // M
                g_M[j] = dot128(pos4 + (j>>4)*32, W4 + (j&15)*32);
            } else if (j < NN*NL + NL*NL) {          // G
                int k = j - NN*NL;
                g_G[k] = dot128(W4 + (k>>4)*32, W4 + (k&15)*32);
            }
        } else {
            if (tid == 0) { while (ld_acq(&g_flag1) == 0) {} }
            __syncthreads();
            const float4* cv4 = (const float4*)g_constvec;
            int j = (pid-35)*128 + tid;
            if (j < NN) {                            // D2
                g_D2[j] = dot128(pos4 + j*32, cv4);
            } else if (j < NN + NL) {                // u
                g_u[j-NN] = dot128(W4 + (j-NN)*32, cv4);
            } else if (j < NN + 2*NL) {              // wb
                g_wb[j-NN-NL] = dot128(W4 + (j-NN-NL)*32, (const float4*)b_enc);
            } else if (j == NN + 2*NL) {             // s0
                g_s0 = dot128((const float4*)b_enc, cv4);
            }
        }
        __threadfence();
        __syncthreads();
        if (tid == 0) atomicAdd(&g_done, 1);
    }

    // ---------- main per-pair work (all 2048 blocks) ----------
    const float4* __restrict__ xp4 = (const float4*)(x + (size_t)pid * XPP);
    float4* __restrict__ xc4 = (float4*)(x_copy + (size_t)pid * XPP);

    // Phase 1: stream x -> registers + fused passthrough copy + xsum partials.
    // Thread (4r+q) holds l-quarter q of rows n = it*32 + r, it = 0..7.
    float4 xv[8];
    float ls0=0.f, ls1=0.f, ls2=0.f, ls3=0.f;
    #pragma unroll
    for (int it = 0; it < 8; it++) {
        int i = tid + it*128;
        if (i < XPP/4) {
            float4 v = __ldcs(xp4 + i);
            __stcs(xc4 + i, v);
            xv[it] = v;
            ls0 += v.x; ls1 += v.y; ls2 += v.z; ls3 += v.w;
        } else {
            xv[it] = make_float4(0.f, 0.f, 0.f, 0.f);
        }
    }

    // xsum reduce: butterfly over q-classes (masks 4,8,16), then cross-warp smem
    #pragma unroll
    for (int m = 4; m <= 16; m <<= 1) {
        ls0 += __shfl_xor_sync(0xffffffffu, ls0, m);
        ls1 += __shfl_xor_sync(0xffffffffu, ls1, m);
        ls2 += __shfl_xor_sync(0xffffffffu, ls2, m);
        ls3 += __shfl_xor_sync(0xffffffffu, ls3, m);
    }
    if (lane < 4) {
        float* rr = &redq[wrp][lane*4];
        rr[0] = ls0; rr[1] = ls1; rr[2] = ls2; rr[3] = ls3;
    }
    __syncthreads();
    if (tid < NL)
        xsumS[tid] = (redq[0][tid] + redq[1][tid]) + (redq[2][tid] + redq[3][tid]);
    if (tid == 64) { while (ld_acq(&g_done) < NPRE) {} }
    __syncthreads();

    // Phase 3: v = G^T xsum + u ; s = xsum.wb + s0
    if (tid < NL) {
        float a = g_u[tid];
        #pragma unroll
        for (int lp = 0; lp < NL; lp++) a += xsumS[lp] * g_G[lp*NL + tid];
        vS[tid] = a;
    }
    if (tid == 16) {
        float a = g_s0;
        #pragma unroll
        for (int l = 0; l < NL; l++) a += xsumS[l] * g_wb[l];
        sS = a;
    }
    if (tid == 127) { sc[254] = 0.f; sc[255] = 0.f; }
    __syncthreads();

    // Phase 4: score[n] = s + D2[n] + x[n].v + xsum.M[n]
    // Each thread: quarter partials, butterfly over lanes {^1, ^2}.
    float4 vq  = ((const float4*)vS)[q];
    float4 xsq = ((const float4*)xsumS)[q];
    float myabs = 0.f;
    float sloc = sS;
    #pragma unroll
    for (int it = 0; it < 8; it++) {
        int n = it*32 + r;
        float part = 0.f;
        if (n < NN) {
            float4 m = *(const float4*)(g_M + n*NL + q*4);
            part = xv[it].x*vq.x + xv[it].y*vq.y + xv[it].z*vq.z + xv[it].w*vq.w
                 + xsq.x*m.x + xsq.y*m.y + xsq.z*m.z + xsq.w*m.w;
        }
        part += __shfl_xor_sync(0xffffffffu, part, 1);
        part += __shfl_xor_sync(0xffffffffu, part, 2);
        if (q == 0 && n < NN) {
            float a = part + sloc + g_D2[n];
            sc[n] = a;
            myabs += fabsf(a);
        }
    }
    // deterministic reduction of sum|score|
    #pragma unroll
    for (int off = 16; off; off >>= 1)
        myabs += __shfl_down_sync(0xffffffffu, myabs, off);
    if (lane == 0) warpsum[wrp] = myabs;
    __syncthreads();
    if (tid == 0)
        invS = 1.0f / ((warpsum[0] + warpsum[1]) + (warpsum[2] + warpsum[3]));

    // Phase 5: pooled[l] = invS * sum_n x[n,l]*score[n]  (register x, smem sc)
    {
        float p0=0.f, p1=0.f, p2=0.f, p3=0.f;
        #pragma unroll
        for (int it = 0; it < 8; it++) {
            int n = it*32 + r;              // n <= 255; sc[254..255]=0
            float w = sc[n];
            p0 += xv[it].x * w;
            p1 += xv[it].y * w;
            p2 += xv[it].z * w;
            p3 += xv[it].w * w;
        }
        #pragma unroll
        for (int m = 4; m <= 16; m <<= 1) {
            p0 += __shfl_xor_sync(0xffffffffu, p0, m);
            p1 += __shfl_xor_sync(0xffffffffu, p1, m);
            p2 += __shfl_xor_sync(0xffffffffu, p2, m);
            p3 += __shfl_xor_sync(0xffffffffu, p3, m);
        }
        if (lane < 4) {
            float* rr = &redq[wrp][lane*4];
            rr[0] = p0; rr[1] = p1; rr[2] = p2; rr[3] = p3;
        }
    }
    __syncthreads();
    if (tid < NL)
        pooledS[tid] = invS * ((redq[0][tid] + redq[1][tid]) + (redq[2][tid] + redq[3][tid]));
    __syncthreads();

    // Phase 6: hidden = leaky_relu(pooled @ W1 + b1, 0.2)   (tid = h)
    {
        float a = b1[tid];
        #pragma unroll
        for (int l = 0; l < NL; l++) a += pooledS[l] * __ldg(W1 + l*NH + tid);
        hdnS[tid] = a > 0.f ? a : 0.2f * a;
    }
    __syncthreads();

    // Phase 7: out[p] = hidden @ W2 + b2. Warp w covers h in [32w,32w+32);
    // lanes 0..23 each hold a float4 of p. Cross-warp reduce via smem.
    if (lane < 24) {
        const float4* __restrict__ W24 = (const float4*)W2;  // [h][24] float4s
        float4 acc = make_float4(0.f, 0.f, 0.f, 0.f);
        #pragma unroll 8
        for (int hh = 0; hh < 32; hh++) {
            int h = wrp*32 + hh;
            float hv = hdnS[h];
            float4 w4 = __ldg(&W24[h*24 + lane]);
            acc.x += hv*w4.x; acc.y += hv*w4.y; acc.z += hv*w4.z; acc.w += hv*w4.w;
        }
        ((float4*)red7[wrp])[lane] = acc;
    }
    __syncthreads();
    if (tid < NP) {
        float a = b2[tid] + (red7[0][tid] + red7[1][tid]) + (red7[2][tid] + red7[3][tid]);
        int b = pid >> 6, d = pid & 63;
        out_t[b*(NP*ND) + tid*ND + d] = a;
    }
}

extern "C" void kernel_launch(void* const* d_in, const int* in_sizes, int n_in,
                              void* d_out, int out_size) {
    const float* x     = (const float*)d_in[0];
    const float* W_enc = (const float*)d_in[1];
    const float* b_enc = (const float*)d_in[2];
    const float* W1    = (const float*)d_in[3];
    const float* b1    = (const float*)d_in[4];
    const float* W2    = (const float*)d_in[5];
    const float* b2    = (const float*)d_in[6];
    const float* pos   = (const float*)d_in[7];

    float* out   = (float*)d_out;          // (B,P,D) first
    float* xcopy = out + OUT_T_ELEMS;      // then p = x passthrough

    k_all<<<PAIRS, 128>>>(x, xcopy, W_enc, b_enc, pos, W1, b1, W2, b2, out);
}